// round 14
// baseline (speedup 1.0000x reference)
#include <cuda_runtime.h>
#include <cuda_bf16.h>
#include <math.h>
#include <stdint.h>

#define G    32
#define NN   2048
#define IND  128
#define LD   64
#define KTOP 64

// ---------------- scratch (device globals; no allocation allowed) ----------
__device__ float d_XW[G * NN * LD];                 // x @ W_gcn  (fp32)
__device__ __nv_bfloat16 d_Bh[G * LD * NN];         // transposed scaled B, hi  [gi][d][j]
__device__ __nv_bfloat16 d_Bl[G * LD * NN];         // transposed scaled B, lo
__device__ float d_invdeg[G * NN];
__device__ float d_hn[G * NN * LD];                 // elu(gn@XW + b) PRE-LayerNorm
__device__ float d_stats[G * 2];
__device__ float d_colsum[G * LD];
__device__ float d_sraw[G * NN];
__device__ int   d_topk[G * KTOP];
__device__ float d_mu[G];
__device__ float d_rsig[G];
__device__ float d_gmean[G * LD];
__device__ float d_subreps[G * KTOP * LD];
__device__ float d_Bout[G * LD];

__device__ __forceinline__ uint32_t s2u(const void* p) {
    uint32_t a;
    asm("{ .reg .u64 t; cvta.to.shared.u64 t, %1; cvt.u32.u64 %0, t; }" : "=r"(a) : "l"(p));
    return a;
}
__device__ __forceinline__ void mma16816(float* d, const uint32_t* a,
                                         uint32_t b0, uint32_t b1) {
    asm volatile(
        "mma.sync.aligned.m16n8k16.row.col.f32.bf16.bf16.f32 "
        "{%0,%1,%2,%3}, {%4,%5,%6,%7}, {%8,%9}, {%0,%1,%2,%3};"
        : "+f"(d[0]), "+f"(d[1]), "+f"(d[2]), "+f"(d[3])
        : "r"(a[0]), "r"(a[1]), "r"(a[2]), "r"(a[3]), "r"(b0), "r"(b1));
}
// NON-transposed ldmatrix: smem tile is [n][k] (k contiguous) == B col-major
#define LDMX4(r, addr) \
    asm volatile("ldmatrix.sync.aligned.m8n8.x4.shared.b16 {%0,%1,%2,%3}, [%4];" \
        : "=r"((r)[0]), "=r"((r)[1]), "=r"((r)[2]), "=r"((r)[3]) : "r"(addr))

__device__ __forceinline__ uint32_t pack_hi(float x, float y) {
    __nv_bfloat162 h = __floats2bfloat162_rn(x, y);
    return *(uint32_t*)&h;
}
__device__ __forceinline__ uint32_t pack_lo(float x, float y, uint32_t hi) {
    __nv_bfloat162 h = *(__nv_bfloat162*)&hi;
    float2 f = __bfloat1622float2(h);
    __nv_bfloat162 l = __floats2bfloat162_rn(x - f.x, y - f.y);
    return *(uint32_t*)&l;
}

// ---------------- kernel 1: inverse degrees + accumulator init -------------
__global__ void k_deg(const float* __restrict__ g) {
    if (blockIdx.x == 0) {
        for (int i = threadIdx.x; i < G * 2; i += blockDim.x) d_stats[i] = 0.f;
        for (int i = threadIdx.x; i < G * LD; i += blockDim.x) d_colsum[i] = 0.f;
    }
    int warp = (blockIdx.x * blockDim.x + threadIdx.x) >> 5;
    int lane = threadIdx.x & 31;
    if (warp >= G * NN) return;
    const float* row = g + (size_t)warp * NN;
    float s = 0.f;
    #pragma unroll
    for (int c = lane * 4; c < NN; c += 128) {
        float4 v = *(const float4*)(row + c);
        s += v.x + v.y + v.z + v.w;
    }
    #pragma unroll
    for (int o = 16; o; o >>= 1) s += __shfl_xor_sync(0xFFFFFFFFu, s, o);
    if (lane == 0) d_invdeg[warp] = 1.0f / s;
}

// ---------------- kernel 2: XW = x @ W_gcn  (128x64 tile, 8x8/thread) ------
__global__ void __launch_bounds__(128) k_xw(const float* __restrict__ x,
                                            const float* __restrict__ W) {
    const int tid = threadIdx.x;
    const int gi = blockIdx.x >> 4;
    const int rb = blockIdx.x & 15;
    const int ty = tid >> 3, tx = tid & 7;
    __shared__ float As[32][132];
    __shared__ float Bs[32][64];
    const float* A = x + ((size_t)gi * NN + (size_t)rb * 128) * IND;
    float acc[8][8];
    #pragma unroll
    for (int r = 0; r < 8; r++)
        #pragma unroll
        for (int c = 0; c < 8; c++) acc[r][c] = 0.f;

    for (int k0 = 0; k0 < IND; k0 += 32) {
        #pragma unroll
        for (int l = 0; l < 8; l++) {
            int s = tid + l * 128;
            int row = s >> 3, cq = s & 7;
            float4 v = *(const float4*)(A + (size_t)row * IND + k0 + cq * 4);
            As[cq * 4 + 0][row] = v.x; As[cq * 4 + 1][row] = v.y;
            As[cq * 4 + 2][row] = v.z; As[cq * 4 + 3][row] = v.w;
        }
        #pragma unroll
        for (int l = 0; l < 4; l++) {
            int s = tid + l * 128;
            int row = s >> 4, cq = s & 15;
            float4 v = *(const float4*)(W + (size_t)(k0 + row) * LD + cq * 4);
            *(float4*)&Bs[row][cq * 4] = v;
        }
        __syncthreads();
        #pragma unroll
        for (int kk = 0; kk < 32; kk++) {
            float a[8], b[8];
            *(float4*)&a[0] = *(const float4*)&As[kk][ty * 8];
            *(float4*)&a[4] = *(const float4*)&As[kk][ty * 8 + 4];
            *(float4*)&b[0] = *(const float4*)&Bs[kk][tx * 8];
            *(float4*)&b[4] = *(const float4*)&Bs[kk][tx * 8 + 4];
            #pragma unroll
            for (int r = 0; r < 8; r++)
                #pragma unroll
                for (int c = 0; c < 8; c++) acc[r][c] = fmaf(a[r], b[c], acc[r][c]);
        }
        __syncthreads();
    }
    float* out = d_XW + ((size_t)gi * NN + (size_t)rb * 128) * LD;
    #pragma unroll
    for (int r = 0; r < 8; r++) {
        int row = ty * 8 + r;
        float4 v0 = make_float4(acc[r][0], acc[r][1], acc[r][2], acc[r][3]);
        float4 v1 = make_float4(acc[r][4], acc[r][5], acc[r][6], acc[r][7]);
        *(float4*)(out + (size_t)row * LD + tx * 8)     = v0;
        *(float4*)(out + (size_t)row * LD + tx * 8 + 4) = v1;
    }
}

// ------- kernel 2b: B' = transpose(XW * invdeg) split into bf16 hi/lo ------
__global__ void __launch_bounds__(256) k_prepB() {
    __shared__ float T[64][65];
    int gi = blockIdx.x >> 5, jb = blockIdx.x & 31;
    int tid = threadIdx.x;
    const float* src = d_XW + ((size_t)gi * NN + (size_t)jb * 64) * LD;
    const float* idg = d_invdeg + gi * NN + jb * 64;
    #pragma unroll
    for (int t = 0; t < 4; t++) {
        int s = tid + t * 256;
        int j = s >> 4, c4 = (s & 15) * 4;
        float sc = idg[j];
        float4 v = *(const float4*)(src + (size_t)j * LD + c4);
        T[j][c4 + 0] = v.x * sc; T[j][c4 + 1] = v.y * sc;
        T[j][c4 + 2] = v.z * sc; T[j][c4 + 3] = v.w * sc;
    }
    __syncthreads();
    #pragma unroll
    for (int t = 0; t < 4; t++) {
        int s = tid + t * 256;
        int d = s >> 4, j4 = (s & 15) * 4;
        float v0 = T[j4 + 0][d], v1 = T[j4 + 1][d];
        float v2 = T[j4 + 2][d], v3 = T[j4 + 3][d];
        uint32_t h01 = pack_hi(v0, v1);
        uint32_t h23 = pack_hi(v2, v3);
        uint32_t l01 = pack_lo(v0, v1, h01);
        uint32_t l23 = pack_lo(v2, v3, h23);
        size_t o = ((size_t)gi * LD + d) * NN + (size_t)jb * 64 + j4;
        *(uint2*)(d_Bh + o) = make_uint2(h01, h23);
        *(uint2*)(d_Bl + o) = make_uint2(l01, l23);
    }
}

// ---------- kernel 3: hn = elu(g @ B' + b) + fused LN-stats/scores ---------
// CTA: 256 thr = 8 warps; tile 256(M) x 64(N); warp w -> rows w*32..+31.
// K-chunks of 128, cp.async double-buffered B staging.
#define BK 128
#define BP 136                               // bf16 pitch: 272B = 17*16B
#define BUFB (64 * BP * 2)                   // bytes per (buf,part) plane
__global__ void __launch_bounds__(256) k_hn_mma(const float* __restrict__ g,
                                                const float* __restrict__ bg,
                                                const float* __restrict__ psel) {
    extern __shared__ __nv_bfloat16 Bsm[];   // [2 buf][2 part][64][BP]
    __shared__ float s_ps[64], s_bs[64], s_col[64], s_red[8][2];
    const int tid = threadIdx.x, lane = tid & 31, w = tid >> 5;
    const int gi = blockIdx.x >> 3, rb = blockIdx.x & 7;
    const int gid = lane >> 2, q = lane & 3;
    const __nv_bfloat16* Bh = d_Bh + (size_t)gi * LD * NN;
    const __nv_bfloat16* Bl = d_Bl + (size_t)gi * LD * NN;
    const int wb = rb * 256 + w * 32;
    const float* Abase = g + ((size_t)gi * NN + wb + gid) * NN;

    if (tid < 64) { s_ps[tid] = psel[tid]; s_bs[tid] = bg[tid]; s_col[tid] = 0.f; }

    float acc[2][8][4];
    #pragma unroll
    for (int mt = 0; mt < 2; mt++)
        #pragma unroll
        for (int j = 0; j < 8; j++)
            #pragma unroll
            for (int c = 0; c < 4; c++) acc[mt][j][c] = 0.f;

    const uint32_t smem0 = s2u(Bsm);
    const int lgrp = lane >> 3, lrow = lane & 7;
    const uint32_t lmo = (uint32_t)((((lgrp & 2) << 2) + lrow) * (BP * 2)
                                    + (lgrp & 1) * 16);

    // issue one K-chunk's B (hi+lo) via cp.async: 2048 x 16B, 8 per thread
    #define ISSUE_B(cc) do {                                                   \
        int b_ = (cc) & 1;                                                     \
        int k0_ = (cc) * BK;                                                   \
        _Pragma("unroll")                                                      \
        for (int t_ = 0; t_ < 8; t_++) {                                       \
            int s_ = tid + t_ * 256;                                           \
            int part_ = s_ >> 10;                                              \
            int row_ = (s_ >> 4) & 63;                                         \
            int seg_ = s_ & 15;                                                \
            const __nv_bfloat16* src_ = (part_ ? Bl : Bh)                      \
                + (size_t)row_ * NN + k0_ + seg_ * 8;                          \
            uint32_t dst_ = smem0 + (uint32_t)((b_ * 2 + part_) * BUFB         \
                + row_ * (BP * 2) + seg_ * 16);                                \
            asm volatile("cp.async.cg.shared.global [%0], [%1], 16;"           \
                         :: "r"(dst_), "l"(src_));                             \
        }                                                                      \
        asm volatile("cp.async.commit_group;");                                \
    } while (0)

    ISSUE_B(0);
    for (int c = 0; c < 16; c++) {
        if (c + 1 < 16) {
            ISSUE_B(c + 1);
            asm volatile("cp.async.wait_group 1;");
        } else {
            asm volatile("cp.async.wait_group 0;");
        }
        __syncthreads();                       // buf c ready
        const int b = c & 1;
        const uint32_t hiB = smem0 + (uint32_t)((b * 2 + 0) * BUFB) + lmo;
        const uint32_t loB = smem0 + (uint32_t)((b * 2 + 1) * BUFB) + lmo;
        const int k0 = c * BK;
        #pragma unroll
        for (int ks = 0; ks < 8; ks++) {
            const int kk = k0 + ks * 16;
            uint32_t ah[2][4], al[2][4];
            #pragma unroll
            for (int mt = 0; mt < 2; mt++) {
                const float* Ar = Abase + (size_t)(mt * 16) * NN;
                float2 f00 = *(const float2*)(Ar + kk + q * 2);
                float2 f10 = *(const float2*)(Ar + 8 * NN + kk + q * 2);
                float2 f01 = *(const float2*)(Ar + kk + 8 + q * 2);
                float2 f11 = *(const float2*)(Ar + 8 * NN + kk + 8 + q * 2);
                ah[mt][0] = pack_hi(f00.x, f00.y); al[mt][0] = pack_lo(f00.x, f00.y, ah[mt][0]);
                ah[mt][1] = pack_hi(f10.x, f10.y); al[mt][1] = pack_lo(f10.x, f10.y, ah[mt][1]);
                ah[mt][2] = pack_hi(f01.x, f01.y); al[mt][2] = pack_lo(f01.x, f01.y, ah[mt][2]);
                ah[mt][3] = pack_hi(f11.x, f11.y); al[mt][3] = pack_lo(f11.x, f11.y, ah[mt][3]);
            }
            #pragma unroll
            for (int nb = 0; nb < 4; nb++) {
                uint32_t bh[4], bl[4];
                uint32_t off = (uint32_t)(nb * 16 * (BP * 2) + ks * 32);
                LDMX4(bh, hiB + off);
                LDMX4(bl, loB + off);
                #pragma unroll
                for (int mt = 0; mt < 2; mt++) {
                    int j0 = nb * 2, j1 = nb * 2 + 1;
                    mma16816(acc[mt][j0], ah[mt], bh[0], bh[1]);   // hi*hi
                    mma16816(acc[mt][j0], al[mt], bh[0], bh[1]);   // lo*hi
                    mma16816(acc[mt][j0], ah[mt], bl[0], bl[1]);   // hi*lo
                    mma16816(acc[mt][j1], ah[mt], bh[2], bh[3]);
                    mma16816(acc[mt][j1], al[mt], bh[2], bh[3]);
                    mma16816(acc[mt][j1], ah[mt], bl[2], bl[3]);
                }
            }
        }
        __syncthreads();                       // done with buf c before refill
    }

    // ---- fused epilogue: bias+elu+store, row scores, LN stats, col sums ----
    float dots[2][2] = {{0.f, 0.f}, {0.f, 0.f}};
    float sum = 0.f, sq = 0.f;
    float cs0[8], cs1[8];
    #pragma unroll
    for (int j = 0; j < 8; j++) { cs0[j] = 0.f; cs1[j] = 0.f; }

    #pragma unroll
    for (int mt = 0; mt < 2; mt++) {
        float* outr = d_hn + (size_t)(gi * NN + wb + mt * 16 + gid) * LD;
        #pragma unroll
        for (int j = 0; j < 8; j++) {
            int n = j * 8 + q * 2;
            float b0 = s_bs[n], b1 = s_bs[n + 1];
            float h0 = acc[mt][j][0] + b0, h1 = acc[mt][j][1] + b1;
            float h2 = acc[mt][j][2] + b0, h3 = acc[mt][j][3] + b1;
            float v0 = (h0 > 0.f) ? h0 : expm1f(h0);
            float v1 = (h1 > 0.f) ? h1 : expm1f(h1);
            float v2 = (h2 > 0.f) ? h2 : expm1f(h2);
            float v3 = (h3 > 0.f) ? h3 : expm1f(h3);
            float2 o0 = make_float2(v0, v1), o1 = make_float2(v2, v3);
            *(float2*)(outr + n) = o0;
            *(float2*)(outr + 8 * LD + n) = o1;
            float p0 = s_ps[n], p1 = s_ps[n + 1];
            dots[mt][0] += v0 * p0 + v1 * p1;
            dots[mt][1] += v2 * p0 + v3 * p1;
            sum += v0 + v1 + v2 + v3;
            sq += v0 * v0 + v1 * v1 + v2 * v2 + v3 * v3;
            cs0[j] += v0 + v2;
            cs1[j] += v1 + v3;
        }
    }
    // row dots: reduce across q within each quad
    #pragma unroll
    for (int mt = 0; mt < 2; mt++)
        #pragma unroll
        for (int h = 0; h < 2; h++) {
            float d = dots[mt][h];
            d += __shfl_xor_sync(0xFFFFFFFFu, d, 1);
            d += __shfl_xor_sync(0xFFFFFFFFu, d, 2);
            if (q == 0)
                d_sraw[gi * NN + wb + mt * 16 + h * 8 + gid] = d;
        }
    // sum/sq: full warp reduce
    #pragma unroll
    for (int o = 16; o; o >>= 1) {
        sum += __shfl_xor_sync(0xFFFFFFFFu, sum, o);
        sq  += __shfl_xor_sync(0xFFFFFFFFu, sq, o);
    }
    if (lane == 0) { s_red[w][0] = sum; s_red[w][1] = sq; }
    // col sums: reduce across gid (lanes xor 4/8/16 keep q class)
    #pragma unroll
    for (int j = 0; j < 8; j++) {
        float a = cs0[j], b2 = cs1[j];
        a += __shfl_xor_sync(0xFFFFFFFFu, a, 4);
        a += __shfl_xor_sync(0xFFFFFFFFu, a, 8);
        a += __shfl_xor_sync(0xFFFFFFFFu, a, 16);
        b2 += __shfl_xor_sync(0xFFFFFFFFu, b2, 4);
        b2 += __shfl_xor_sync(0xFFFFFFFFu, b2, 8);
        b2 += __shfl_xor_sync(0xFFFFFFFFu, b2, 16);
        if (lane < 4) {
            atomicAdd(&s_col[j * 8 + lane * 2], a);
            atomicAdd(&s_col[j * 8 + lane * 2 + 1], b2);
        }
    }
    __syncthreads();
    if (tid == 0) {
        float a = 0.f, b2 = 0.f;
        #pragma unroll
        for (int i = 0; i < 8; i++) { a += s_red[i][0]; b2 += s_red[i][1]; }
        atomicAdd(&d_stats[gi * 2 + 0], a);
        atomicAdd(&d_stats[gi * 2 + 1], b2);
    }
    if (tid < 64) atomicAdd(&d_colsum[gi * LD + tid], s_col[tid]);
}

// ---------------- kernel 6: LN finalize + bitonic top-k --------------------
__global__ void k_topk() {
    int gi = blockIdx.x, tid = threadIdx.x;
    __shared__ unsigned long long keys[NN];
    const float invM = 1.0f / (float)(NN * LD);
    float mu = d_stats[gi * 2 + 0] * invM;
    float var = d_stats[gi * 2 + 1] * invM - mu * mu;
    float rsig = rsqrtf(var + 1e-5f);
    if (tid == 0) { d_mu[gi] = mu; d_rsig[gi] = rsig; }
    if (tid < LD)
        d_gmean[gi * LD + tid] = (d_colsum[gi * LD + tid] * (1.0f / NN) - mu) * rsig;

    for (int i = tid; i < NN; i += 1024) {
        float s = d_sraw[gi * NN + i];
        unsigned u = __float_as_uint(s);
        u = (u & 0x80000000u) ? ~u : (u | 0x80000000u);
        unsigned long long key = ((unsigned long long)u << 32) | (unsigned)(NN - 1 - i);
        keys[i] = ~key;
    }
    __syncthreads();
    for (int k = 2; k <= NN; k <<= 1) {
        for (int j = k >> 1; j; j >>= 1) {
            for (int i = tid; i < NN; i += 1024) {
                int ixj = i ^ j;
                if (ixj > i) {
                    bool up = ((i & k) == 0);
                    unsigned long long a = keys[i], b = keys[ixj];
                    if ((a > b) == up) { keys[i] = b; keys[ixj] = a; }
                }
            }
            __syncthreads();
        }
    }
    if (tid < KTOP) {
        unsigned long long key = ~keys[tid];
        int idx = (NN - 1) - (int)(key & 0xFFFFFFFFu);
        d_topk[gi * KTOP + tid] = idx;
    }
}

// ---------------- kernel 7: sub_reps = (gn @ hn_norm)[topk] ----------------
__global__ void __launch_bounds__(256) k_sub(const float* __restrict__ g) {
    int gi = blockIdx.x >> 2;
    int rb = blockIdx.x & 3;
    int tid = threadIdx.x;
    __shared__ float As[16][64];
    __shared__ float Bs[64][64];
    __shared__ int rows[16];
    float mu = d_mu[gi], rsig = d_rsig[gi];
    if (tid < 16) rows[tid] = d_topk[gi * KTOP + rb * 16 + tid];
    __syncthreads();
    int col = tid & 63, r0 = (tid >> 6) * 4;
    float acc[4] = {0.f, 0.f, 0.f, 0.f};
    const float* gg  = g + (size_t)gi * NN * NN;
    const float* hh  = d_hn + (size_t)gi * NN * LD;
    const float* idg = d_invdeg + (size_t)gi * NN;

    for (int k0 = 0; k0 < NN; k0 += 64) {
        {
            int rr = tid >> 4, cq = tid & 15;
            float4 v = *(const float4*)(gg + (size_t)rows[rr] * NN + k0 + cq * 4);
            *(float4*)&As[rr][cq * 4] = v;
        }
        #pragma unroll
        for (int l = 0; l < 4; l++) {
            int s = tid + l * 256;
            int j = s >> 4, cq = s & 15;
            float w = rsig * idg[k0 + j];
            float4 v = *(const float4*)(hh + (size_t)(k0 + j) * LD + cq * 4);
            v.x = (v.x - mu) * w; v.y = (v.y - mu) * w;
            v.z = (v.z - mu) * w; v.w = (v.w - mu) * w;
            *(float4*)&Bs[j][cq * 4] = v;
        }
        __syncthreads();
        #pragma unroll 8
        for (int j = 0; j < 64; j++) {
            float b = Bs[j][col];
            acc[0] = fmaf(As[r0 + 0][j], b, acc[0]);
            acc[1] = fmaf(As[r0 + 1][j], b, acc[1]);
            acc[2] = fmaf(As[r0 + 2][j], b, acc[2]);
            acc[3] = fmaf(As[r0 + 3][j], b, acc[3]);
        }
        __syncthreads();
    }
    #pragma unroll
    for (int rr = 0; rr < 4; rr++)
        d_subreps[(size_t)gi * KTOP * LD + (size_t)(rb * 16 + r0 + rr) * LD + col] = acc[rr];
}

// ---------------- kernel 8: ops -> conv -> relu -> maxpool -> alpha mix ----
__global__ void __launch_bounds__(256) k_mix(const float* __restrict__ convk,
                                             const float* __restrict__ convb,
                                             const float* __restrict__ logalpha) {
    int gi = blockIdx.x, tid = threadIdx.x;
    int tx = tid & 15, ty = tid >> 4;
    __shared__ float S[64][66];
    __shared__ float Bt[16][128];
    __shared__ float Pb[16][64];
    __shared__ float Red[16][64];
    __shared__ float gm[64], cb[64], alpha[3], feats[3][64];

    for (int i = tid; i < 4096; i += 256)
        S[i >> 6][i & 63] = d_subreps[(size_t)gi * 4096 + i];
    if (tid < 64) { gm[tid] = d_gmean[gi * LD + tid]; cb[tid] = convb[tid]; }
    if (tid == 0) {
        float a0 = logalpha[0], a1 = logalpha[1], a2 = logalpha[2];
        float m = fmaxf(a0, fmaxf(a1, a2));
        float e0 = expf(a0 - m), e1 = expf(a1 - m), e2 = expf(a2 - m);
        float inv = 1.0f / (e0 + e1 + e2);
        alpha[0] = e0 * inv; alpha[1] = e1 * inv; alpha[2] = e2 * inv;
    }
    __syncthreads();

    const int oorder[3] = {0, 2, 1};
    for (int oo = 0; oo < 3; oo++) {
        int o = oorder[oo];
        if (o == 1) {
            __syncthreads();
            for (int i = tid; i < 4096; i += 256) {
                float v = S[i >> 6][i & 63];
                S[i >> 6][i & 63] = (v > 0.f) ? v : expm1f(v);
            }
        }
        float aq[4][4], ap[4][4];
        #pragma unroll
        for (int r = 0; r < 4; r++)
            #pragma unroll
            for (int c = 0; c < 4; c++) { aq[r][c] = 0.f; ap[r][c] = 0.f; }

        for (int l0 = 0; l0 < 64; l0 += 16) {
            __syncthreads();
            #pragma unroll
            for (int t = 0; t < 2; t++) {
                int s = tid + t * 256;
                int lr = s >> 5, cq = s & 31;
                int dd = cq * 4;
                const float* src = (dd < 64)
                    ? (convk + (size_t)(l0 + lr) * 64 + dd)
                    : (convk + 4096 + (size_t)(l0 + lr) * 64 + (dd - 64));
                *(float4*)&Bt[lr][dd] = *(const float4*)src;
            }
            __syncthreads();
            #pragma unroll
            for (int l = 0; l < 16; l++) {
                float a[4];
                #pragma unroll
                for (int r = 0; r < 4; r++) {
                    float v = S[ty * 4 + r][l0 + l];
                    a[r] = (o == 2) ? v + gm[l0 + l] : v;
                }
                float4 bq = *(const float4*)&Bt[l][tx * 4];
                float4 bp = *(const float4*)&Bt[l][64 + tx * 4];
                #pragma unroll
                for (int r = 0; r < 4; r++) {
                    aq[r][0] = fmaf(a[r], bq.x, aq[r][0]);
                    aq[r][1] = fmaf(a[r], bq.y, aq[r][1]);
                    aq[r][2] = fmaf(a[r], bq.z, aq[r][2]);
                    aq[r][3] = fmaf(a[r], bq.w, aq[r][3]);
                    ap[r][0] = fmaf(a[r], bp.x, ap[r][0]);
                    ap[r][1] = fmaf(a[r], bp.y, ap[r][1]);
                    ap[r][2] = fmaf(a[r], bp.z, ap[r][2]);
                    ap[r][3] = fmaf(a[r], bp.w, ap[r][3]);
                }
            }
        }
        __syncthreads();
        #pragma unroll
        for (int c = 0; c < 4; c++) Pb[ty][tx * 4 + c] = ap[0][c];
        __syncthreads();
        float vm[4] = {0.f, 0.f, 0.f, 0.f};
        #pragma unroll
        for (int r = 0; r < 4; r++) {
            int k = ty * 4 + r;
            if (k <= 62) {
                float pn[4];
                if (r < 3) {
                    #pragma unroll
                    for (int c = 0; c < 4; c++) pn[c] = ap[r + 1][c];
                } else {
                    #pragma unroll
                    for (int c = 0; c < 4; c++) pn[c] = Pb[ty + 1][tx * 4 + c];
                }
                #pragma unroll
                for (int c = 0; c < 4; c++) {
                    float v = aq[r][c] + pn[c] + cb[tx * 4 + c];
                    v = fmaxf(v, 0.f);
                    vm[c] = fmaxf(vm[c], v);
                }
            }
        }
        #pragma unroll
        for (int c = 0; c < 4; c++) Red[ty][tx * 4 + c] = vm[c];
        __syncthreads();
        if (ty == 0) {
            #pragma unroll
            for (int c = 0; c < 4; c++) {
                float m = 0.f;
                #pragma unroll
                for (int yy = 0; yy < 16; yy++) m = fmaxf(m, Red[yy][tx * 4 + c]);
                feats[o][tx * 4 + c] = m;
            }
        }
        __syncthreads();
    }
    if (tid < 64)
        d_Bout[gi * LD + tid] = alpha[0] * feats[0][tid]
                              + alpha[1] * feats[1][tid]
                              + alpha[2] * feats[2][tid];
}

// ---------------- kernel 9: discriminator epilogue --------------------------
__global__ void k_final(const float* __restrict__ original,
                        const float* __restrict__ Wd,
                        float* __restrict__ out) {
    int tid = threadIdx.x;
    __shared__ float sO[32][64];
    __shared__ float sW[64][64];
    __shared__ float sWc[32][64];
    __shared__ float sB[32][64];
    for (int i = tid; i < 2048; i += 256) {
        sO[i >> 6][i & 63] = original[i];
        sB[i >> 6][i & 63] = d_Bout[i];
    }
    for (int i = tid; i < 4096; i += 256) sW[i >> 6][i & 63] = Wd[i];
    __syncthreads();
    for (int i = tid; i < 2048; i += 256) {
        int gi = i >> 6, d = i & 63;
        float s = 0.f;
        #pragma unroll
        for (int l = 0; l < 64; l++) s = fmaf(sO[gi][l], sW[l][d], s);
        sWc[gi][d] = s;
    }
    __syncthreads();
    if (tid < 32) {
        int i = tid, j = (tid + 31) & 31;
        float s1 = 0.f, s2 = 0.f;
        #pragma unroll
        for (int d = 0; d < 64; d++) {
            s1 = fmaf(sB[i][d], sWc[i][d], s1);
            s2 = fmaf(sB[j][d], sWc[i][d], s2);
        }
        out[i] = s1;
        out[32 + i] = s2;
    }
}

// ---------------- launch ----------------------------------------------------
extern "C" void kernel_launch(void* const* d_in, const int* in_sizes, int n_in,
                              void* d_out, int out_size) {
    const float* original  = (const float*)d_in[0];
    const float* x         = (const float*)d_in[1];
    const float* g         = (const float*)d_in[2];
    const float* W_gcn     = (const float*)d_in[3];
    const float* b_gcn     = (const float*)d_in[4];
    const float* p_select  = (const float*)d_in[5];
    const float* conv_k    = (const float*)d_in[6];
    const float* conv_b    = (const float*)d_in[7];
    const float* W_disc    = (const float*)d_in[8];
    const float* log_alpha = (const float*)d_in[9];
    float* out = (float*)d_out;

    const int hn_smem = 2 * 2 * 64 * BP * 2;   // 69632 bytes
    cudaFuncSetAttribute(k_hn_mma, cudaFuncAttributeMaxDynamicSharedMemorySize, hn_smem);

    k_deg<<<(G * NN) / 8, 256>>>(g);
    k_xw<<<G * (NN / 128), 128>>>(x, W_gcn);
    k_prepB<<<G * 32, 256>>>();
    k_hn_mma<<<G * 8, 256, hn_smem>>>(g, b_gcn, p_select);
    k_topk<<<G, 1024>>>();
    k_sub<<<G * 4, 256>>>(g);
    k_mix<<<G, 256>>>(conv_k, conv_b, log_alpha);
    k_final<<<1, 256>>>(original, W_disc, out);
}

// round 15
// speedup vs baseline: 1.1182x; 1.1182x over previous
#include <cuda_runtime.h>
#include <cuda_bf16.h>
#include <math.h>
#include <stdint.h>

#define G    32
#define NN   2048
#define IND  128
#define LD   64
#define KTOP 64

// ---------------- scratch (device globals; no allocation allowed) ----------
__device__ float d_XW[G * NN * LD];                 // x @ W_gcn  (fp32)
__device__ __nv_bfloat16 d_Bh[G * LD * NN];         // transposed scaled B, hi  [gi][d][j]
__device__ __nv_bfloat16 d_Bl[G * LD * NN];         // transposed scaled B, lo
__device__ float d_invdeg[G * NN];
__device__ float d_hn[G * NN * LD];                 // elu(gn@XW + b) PRE-LayerNorm
__device__ float d_stats[G * 2];
__device__ float d_colsum[G * LD];
__device__ float d_sraw[G * NN];
__device__ int   d_topk[G * KTOP];
__device__ float d_mu[G];
__device__ float d_rsig[G];
__device__ float d_gmean[G * LD];
__device__ float d_subreps[G * KTOP * LD];
__device__ float d_Bout[G * LD];

__device__ __forceinline__ uint32_t s2u(const void* p) {
    uint32_t a;
    asm("{ .reg .u64 t; cvta.to.shared.u64 t, %1; cvt.u32.u64 %0, t; }" : "=r"(a) : "l"(p));
    return a;
}
__device__ __forceinline__ void mma16816(float* d, const uint32_t* a,
                                         uint32_t b0, uint32_t b1) {
    asm volatile(
        "mma.sync.aligned.m16n8k16.row.col.f32.bf16.bf16.f32 "
        "{%0,%1,%2,%3}, {%4,%5,%6,%7}, {%8,%9}, {%0,%1,%2,%3};"
        : "+f"(d[0]), "+f"(d[1]), "+f"(d[2]), "+f"(d[3])
        : "r"(a[0]), "r"(a[1]), "r"(a[2]), "r"(a[3]), "r"(b0), "r"(b1));
}
// NON-transposed ldmatrix: smem tile is [n][k] (k contiguous) == B col-major
#define LDMX4(r, addr) \
    asm volatile("ldmatrix.sync.aligned.m8n8.x4.shared.b16 {%0,%1,%2,%3}, [%4];" \
        : "=r"((r)[0]), "=r"((r)[1]), "=r"((r)[2]), "=r"((r)[3]) : "r"(addr))

__device__ __forceinline__ uint32_t pack_hi(float x, float y) {
    __nv_bfloat162 h = __floats2bfloat162_rn(x, y);
    return *(uint32_t*)&h;
}
__device__ __forceinline__ uint32_t pack_lo(float x, float y, uint32_t hi) {
    __nv_bfloat162 h = *(__nv_bfloat162*)&hi;
    float2 f = __bfloat1622float2(h);
    __nv_bfloat162 l = __floats2bfloat162_rn(x - f.x, y - f.y);
    return *(uint32_t*)&l;
}

// ---------------- kernel 1: inverse degrees + accumulator init -------------
__global__ void k_deg(const float* __restrict__ g) {
    if (blockIdx.x == 0) {
        for (int i = threadIdx.x; i < G * 2; i += blockDim.x) d_stats[i] = 0.f;
        for (int i = threadIdx.x; i < G * LD; i += blockDim.x) d_colsum[i] = 0.f;
    }
    int warp = (blockIdx.x * blockDim.x + threadIdx.x) >> 5;
    int lane = threadIdx.x & 31;
    if (warp >= G * NN) return;
    const float* row = g + (size_t)warp * NN;
    float s = 0.f;
    #pragma unroll
    for (int c = lane * 4; c < NN; c += 128) {
        float4 v = *(const float4*)(row + c);
        s += v.x + v.y + v.z + v.w;
    }
    #pragma unroll
    for (int o = 16; o; o >>= 1) s += __shfl_xor_sync(0xFFFFFFFFu, s, o);
    if (lane == 0) d_invdeg[warp] = 1.0f / s;
}

// ---------------- kernel 2: XW = x @ W_gcn  (128x64 tile, 8x8/thread) ------
__global__ void __launch_bounds__(128) k_xw(const float* __restrict__ x,
                                            const float* __restrict__ W) {
    const int tid = threadIdx.x;
    const int gi = blockIdx.x >> 4;
    const int rb = blockIdx.x & 15;
    const int ty = tid >> 3, tx = tid & 7;
    __shared__ float As[32][132];
    __shared__ float Bs[32][64];
    const float* A = x + ((size_t)gi * NN + (size_t)rb * 128) * IND;
    float acc[8][8];
    #pragma unroll
    for (int r = 0; r < 8; r++)
        #pragma unroll
        for (int c = 0; c < 8; c++) acc[r][c] = 0.f;

    for (int k0 = 0; k0 < IND; k0 += 32) {
        #pragma unroll
        for (int l = 0; l < 8; l++) {
            int s = tid + l * 128;
            int row = s >> 3, cq = s & 7;
            float4 v = *(const float4*)(A + (size_t)row * IND + k0 + cq * 4);
            As[cq * 4 + 0][row] = v.x; As[cq * 4 + 1][row] = v.y;
            As[cq * 4 + 2][row] = v.z; As[cq * 4 + 3][row] = v.w;
        }
        #pragma unroll
        for (int l = 0; l < 4; l++) {
            int s = tid + l * 128;
            int row = s >> 4, cq = s & 15;
            float4 v = *(const float4*)(W + (size_t)(k0 + row) * LD + cq * 4);
            *(float4*)&Bs[row][cq * 4] = v;
        }
        __syncthreads();
        #pragma unroll
        for (int kk = 0; kk < 32; kk++) {
            float a[8], b[8];
            *(float4*)&a[0] = *(const float4*)&As[kk][ty * 8];
            *(float4*)&a[4] = *(const float4*)&As[kk][ty * 8 + 4];
            *(float4*)&b[0] = *(const float4*)&Bs[kk][tx * 8];
            *(float4*)&b[4] = *(const float4*)&Bs[kk][tx * 8 + 4];
            #pragma unroll
            for (int r = 0; r < 8; r++)
                #pragma unroll
                for (int c = 0; c < 8; c++) acc[r][c] = fmaf(a[r], b[c], acc[r][c]);
        }
        __syncthreads();
    }
    float* out = d_XW + ((size_t)gi * NN + (size_t)rb * 128) * LD;
    #pragma unroll
    for (int r = 0; r < 8; r++) {
        int row = ty * 8 + r;
        float4 v0 = make_float4(acc[r][0], acc[r][1], acc[r][2], acc[r][3]);
        float4 v1 = make_float4(acc[r][4], acc[r][5], acc[r][6], acc[r][7]);
        *(float4*)(out + (size_t)row * LD + tx * 8)     = v0;
        *(float4*)(out + (size_t)row * LD + tx * 8 + 4) = v1;
    }
}

// ------- kernel 2b: B' = transpose(XW * invdeg) split into bf16 hi/lo ------
__global__ void __launch_bounds__(256) k_prepB() {
    __shared__ float T[64][65];
    int gi = blockIdx.x >> 5, jb = blockIdx.x & 31;
    int tid = threadIdx.x;
    const float* src = d_XW + ((size_t)gi * NN + (size_t)jb * 64) * LD;
    const float* idg = d_invdeg + gi * NN + jb * 64;
    #pragma unroll
    for (int t = 0; t < 4; t++) {
        int s = tid + t * 256;
        int j = s >> 4, c4 = (s & 15) * 4;
        float sc = idg[j];
        float4 v = *(const float4*)(src + (size_t)j * LD + c4);
        T[j][c4 + 0] = v.x * sc; T[j][c4 + 1] = v.y * sc;
        T[j][c4 + 2] = v.z * sc; T[j][c4 + 3] = v.w * sc;
    }
    __syncthreads();
    #pragma unroll
    for (int t = 0; t < 4; t++) {
        int s = tid + t * 256;
        int d = s >> 4, j4 = (s & 15) * 4;
        float v0 = T[j4 + 0][d], v1 = T[j4 + 1][d];
        float v2 = T[j4 + 2][d], v3 = T[j4 + 3][d];
        uint32_t h01 = pack_hi(v0, v1);
        uint32_t h23 = pack_hi(v2, v3);
        uint32_t l01 = pack_lo(v0, v1, h01);
        uint32_t l23 = pack_lo(v2, v3, h23);
        size_t o = ((size_t)gi * LD + d) * NN + (size_t)jb * 64 + j4;
        *(uint2*)(d_Bh + o) = make_uint2(h01, h23);
        *(uint2*)(d_Bl + o) = make_uint2(l01, l23);
    }
}

// ---------- kernel 3: hn = elu(g @ B' + b) + fused LN-stats/scores ---------
// CTA: 256 thr = 8 warps; tile 128(M) x 64(N); warp w -> rows w*16..+15.
// K-chunks of 128, cp.async double-buffered B staging, A prefetch 1 step.
// 2 CTAs/SM (occupancy was the R14 bottleneck).
#define BK 128
#define BP 136                               // bf16 pitch: 272B = 17*16B
#define BUFB (64 * BP * 2)                   // bytes per (buf,part) plane
__global__ void __launch_bounds__(256, 2) k_hn_mma(const float* __restrict__ g,
                                                   const float* __restrict__ bg,
                                                   const float* __restrict__ psel) {
    extern __shared__ __nv_bfloat16 Bsm[];   // [2 buf][2 part][64][BP]
    __shared__ float s_ps[64], s_bs[64], s_col[64], s_red[8][2];
    const int tid = threadIdx.x, lane = tid & 31, w = tid >> 5;
    const int gi = blockIdx.x >> 4, rb = blockIdx.x & 15;
    const int gid = lane >> 2, q = lane & 3;
    const __nv_bfloat16* Bh = d_Bh + (size_t)gi * LD * NN;
    const __nv_bfloat16* Bl = d_Bl + (size_t)gi * LD * NN;
    const int wb = rb * 128 + w * 16;
    const float* Abase = g + ((size_t)gi * NN + wb + gid) * NN;

    if (tid < 64) { s_ps[tid] = psel[tid]; s_bs[tid] = bg[tid]; s_col[tid] = 0.f; }

    float acc[8][4];
    #pragma unroll
    for (int j = 0; j < 8; j++)
        #pragma unroll
        for (int c = 0; c < 4; c++) acc[j][c] = 0.f;

    const uint32_t smem0 = s2u(Bsm);
    const int lgrp = lane >> 3, lrow = lane & 7;
    const uint32_t lmo = (uint32_t)((((lgrp & 2) << 2) + lrow) * (BP * 2)
                                    + (lgrp & 1) * 16);

    // issue one K-chunk's B (hi+lo) via cp.async: 2048 x 16B, 8 per thread
    #define ISSUE_B(cc) do {                                                   \
        int b_ = (cc) & 1;                                                     \
        int k0_ = (cc) * BK;                                                   \
        _Pragma("unroll")                                                      \
        for (int t_ = 0; t_ < 8; t_++) {                                       \
            int s_ = tid + t_ * 256;                                           \
            int part_ = s_ >> 10;                                              \
            int row_ = (s_ >> 4) & 63;                                         \
            int seg_ = s_ & 15;                                                \
            const __nv_bfloat16* src_ = (part_ ? Bl : Bh)                      \
                + (size_t)row_ * NN + k0_ + seg_ * 8;                          \
            uint32_t dst_ = smem0 + (uint32_t)((b_ * 2 + part_) * BUFB         \
                + row_ * (BP * 2) + seg_ * 16);                                \
            asm volatile("cp.async.cg.shared.global [%0], [%1], 16;"           \
                         :: "r"(dst_), "l"(src_));                             \
        }                                                                      \
        asm volatile("cp.async.commit_group;");                                \
    } while (0)

    // A-fragment prefetch (one k16-step ahead)
    float2 pf0, pf1, pf2, pf3;
    #define LOAD_PF(kkv) do {                                                  \
        pf0 = *(const float2*)(Abase + (kkv) + q * 2);                         \
        pf1 = *(const float2*)(Abase + 8 * NN + (kkv) + q * 2);                \
        pf2 = *(const float2*)(Abase + (kkv) + 8 + q * 2);                     \
        pf3 = *(const float2*)(Abase + 8 * NN + (kkv) + 8 + q * 2);            \
    } while (0)

    ISSUE_B(0);
    LOAD_PF(0);
    for (int c = 0; c < 16; c++) {
        if (c + 1 < 16) {
            ISSUE_B(c + 1);
            asm volatile("cp.async.wait_group 1;");
        } else {
            asm volatile("cp.async.wait_group 0;");
        }
        __syncthreads();                       // buf c ready
        const int b = c & 1;
        const uint32_t hiB = smem0 + (uint32_t)((b * 2 + 0) * BUFB) + lmo;
        const uint32_t loB = smem0 + (uint32_t)((b * 2 + 1) * BUFB) + lmo;
        #pragma unroll
        for (int ks = 0; ks < 8; ks++) {
            float2 f00 = pf0, f10 = pf1, f01 = pf2, f11 = pf3;
            const int nkt = c * 8 + ks + 1;
            LOAD_PF(nkt < 128 ? nkt * 16 : 0);
            uint32_t ah[4], al[4];
            ah[0] = pack_hi(f00.x, f00.y); al[0] = pack_lo(f00.x, f00.y, ah[0]);
            ah[1] = pack_hi(f10.x, f10.y); al[1] = pack_lo(f10.x, f10.y, ah[1]);
            ah[2] = pack_hi(f01.x, f01.y); al[2] = pack_lo(f01.x, f01.y, ah[2]);
            ah[3] = pack_hi(f11.x, f11.y); al[3] = pack_lo(f11.x, f11.y, ah[3]);
            #pragma unroll
            for (int nb = 0; nb < 4; nb++) {
                uint32_t bh[4], bl[4];
                uint32_t off = (uint32_t)(nb * 16 * (BP * 2) + ks * 32);
                LDMX4(bh, hiB + off);
                LDMX4(bl, loB + off);
                int j0 = nb * 2, j1 = nb * 2 + 1;
                mma16816(acc[j0], ah, bh[0], bh[1]);   // hi*hi
                mma16816(acc[j0], al, bh[0], bh[1]);   // lo*hi
                mma16816(acc[j0], ah, bl[0], bl[1]);   // hi*lo
                mma16816(acc[j1], ah, bh[2], bh[3]);
                mma16816(acc[j1], al, bh[2], bh[3]);
                mma16816(acc[j1], ah, bl[2], bl[3]);
            }
        }
        __syncthreads();                       // done with buf c before refill
    }

    // ---- fused epilogue: bias+elu+store, row scores, LN stats, col sums ----
    float dots[2] = {0.f, 0.f};
    float sum = 0.f, sq = 0.f;
    float cs0[8], cs1[8];
    #pragma unroll
    for (int j = 0; j < 8; j++) { cs0[j] = 0.f; cs1[j] = 0.f; }

    {
        float* outr = d_hn + (size_t)(gi * NN + wb + gid) * LD;
        #pragma unroll
        for (int j = 0; j < 8; j++) {
            int n = j * 8 + q * 2;
            float b0 = s_bs[n], b1 = s_bs[n + 1];
            float h0 = acc[j][0] + b0, h1 = acc[j][1] + b1;
            float h2 = acc[j][2] + b0, h3 = acc[j][3] + b1;
            float v0 = (h0 > 0.f) ? h0 : expm1f(h0);
            float v1 = (h1 > 0.f) ? h1 : expm1f(h1);
            float v2 = (h2 > 0.f) ? h2 : expm1f(h2);
            float v3 = (h3 > 0.f) ? h3 : expm1f(h3);
            *(float2*)(outr + n) = make_float2(v0, v1);
            *(float2*)(outr + 8 * LD + n) = make_float2(v2, v3);
            float p0 = s_ps[n], p1 = s_ps[n + 1];
            dots[0] += v0 * p0 + v1 * p1;
            dots[1] += v2 * p0 + v3 * p1;
            sum += v0 + v1 + v2 + v3;
            sq += v0 * v0 + v1 * v1 + v2 * v2 + v3 * v3;
            cs0[j] += v0 + v2;
            cs1[j] += v1 + v3;
        }
    }
    // row dots: reduce across q within each quad
    #pragma unroll
    for (int h = 0; h < 2; h++) {
        float d = dots[h];
        d += __shfl_xor_sync(0xFFFFFFFFu, d, 1);
        d += __shfl_xor_sync(0xFFFFFFFFu, d, 2);
        if (q == 0)
            d_sraw[gi * NN + wb + h * 8 + gid] = d;
    }
    // sum/sq: full warp reduce
    #pragma unroll
    for (int o = 16; o; o >>= 1) {
        sum += __shfl_xor_sync(0xFFFFFFFFu, sum, o);
        sq  += __shfl_xor_sync(0xFFFFFFFFu, sq, o);
    }
    if (lane == 0) { s_red[w][0] = sum; s_red[w][1] = sq; }
    // col sums: reduce across gid (lanes xor 4/8/16 keep q class)
    #pragma unroll
    for (int j = 0; j < 8; j++) {
        float a = cs0[j], b2 = cs1[j];
        a += __shfl_xor_sync(0xFFFFFFFFu, a, 4);
        a += __shfl_xor_sync(0xFFFFFFFFu, a, 8);
        a += __shfl_xor_sync(0xFFFFFFFFu, a, 16);
        b2 += __shfl_xor_sync(0xFFFFFFFFu, b2, 4);
        b2 += __shfl_xor_sync(0xFFFFFFFFu, b2, 8);
        b2 += __shfl_xor_sync(0xFFFFFFFFu, b2, 16);
        if (lane < 4) {
            atomicAdd(&s_col[j * 8 + lane * 2], a);
            atomicAdd(&s_col[j * 8 + lane * 2 + 1], b2);
        }
    }
    __syncthreads();
    if (tid == 0) {
        float a = 0.f, b2 = 0.f;
        #pragma unroll
        for (int i = 0; i < 8; i++) { a += s_red[i][0]; b2 += s_red[i][1]; }
        atomicAdd(&d_stats[gi * 2 + 0], a);
        atomicAdd(&d_stats[gi * 2 + 1], b2);
    }
    if (tid < 64) atomicAdd(&d_colsum[gi * LD + tid], s_col[tid]);
}

// ---------------- kernel 6: LN finalize + bitonic top-k --------------------
__global__ void k_topk() {
    int gi = blockIdx.x, tid = threadIdx.x;
    __shared__ unsigned long long keys[NN];
    const float invM = 1.0f / (float)(NN * LD);
    float mu = d_stats[gi * 2 + 0] * invM;
    float var = d_stats[gi * 2 + 1] * invM - mu * mu;
    float rsig = rsqrtf(var + 1e-5f);
    if (tid == 0) { d_mu[gi] = mu; d_rsig[gi] = rsig; }
    if (tid < LD)
        d_gmean[gi * LD + tid] = (d_colsum[gi * LD + tid] * (1.0f / NN) - mu) * rsig;

    for (int i = tid; i < NN; i += 1024) {
        float s = d_sraw[gi * NN + i];
        unsigned u = __float_as_uint(s);
        u = (u & 0x80000000u) ? ~u : (u | 0x80000000u);
        unsigned long long key = ((unsigned long long)u << 32) | (unsigned)(NN - 1 - i);
        keys[i] = ~key;
    }
    __syncthreads();
    for (int k = 2; k <= NN; k <<= 1) {
        for (int j = k >> 1; j; j >>= 1) {
            for (int i = tid; i < NN; i += 1024) {
                int ixj = i ^ j;
                if (ixj > i) {
                    bool up = ((i & k) == 0);
                    unsigned long long a = keys[i], b = keys[ixj];
                    if ((a > b) == up) { keys[i] = b; keys[ixj] = a; }
                }
            }
            __syncthreads();
        }
    }
    if (tid < KTOP) {
        unsigned long long key = ~keys[tid];
        int idx = (NN - 1) - (int)(key & 0xFFFFFFFFu);
        d_topk[gi * KTOP + tid] = idx;
    }
}

// ---------------- kernel 7: sub_reps = (gn @ hn_norm)[topk] ----------------
__global__ void __launch_bounds__(256) k_sub(const float* __restrict__ g) {
    int gi = blockIdx.x >> 2;
    int rb = blockIdx.x & 3;
    int tid = threadIdx.x;
    __shared__ float As[16][64];
    __shared__ float Bs[64][64];
    __shared__ int rows[16];
    float mu = d_mu[gi], rsig = d_rsig[gi];
    if (tid < 16) rows[tid] = d_topk[gi * KTOP + rb * 16 + tid];
    __syncthreads();
    int col = tid & 63, r0 = (tid >> 6) * 4;
    float acc[4] = {0.f, 0.f, 0.f, 0.f};
    const float* gg  = g + (size_t)gi * NN * NN;
    const float* hh  = d_hn + (size_t)gi * NN * LD;
    const float* idg = d_invdeg + (size_t)gi * NN;

    for (int k0 = 0; k0 < NN; k0 += 64) {
        {
            int rr = tid >> 4, cq = tid & 15;
            float4 v = *(const float4*)(gg + (size_t)rows[rr] * NN + k0 + cq * 4);
            *(float4*)&As[rr][cq * 4] = v;
        }
        #pragma unroll
        for (int l = 0; l < 4; l++) {
            int s = tid + l * 256;
            int j = s >> 4, cq = s & 15;
            float w = rsig * idg[k0 + j];
            float4 v = *(const float4*)(hh + (size_t)(k0 + j) * LD + cq * 4);
            v.x = (v.x - mu) * w; v.y = (v.y - mu) * w;
            v.z = (v.z - mu) * w; v.w = (v.w - mu) * w;
            *(float4*)&Bs[j][cq * 4] = v;
        }
        __syncthreads();
        #pragma unroll 8
        for (int j = 0; j < 64; j++) {
            float b = Bs[j][col];
            acc[0] = fmaf(As[r0 + 0][j], b, acc[0]);
            acc[1] = fmaf(As[r0 + 1][j], b, acc[1]);
            acc[2] = fmaf(As[r0 + 2][j], b, acc[2]);
            acc[3] = fmaf(As[r0 + 3][j], b, acc[3]);
        }
        __syncthreads();
    }
    #pragma unroll
    for (int rr = 0; rr < 4; rr++)
        d_subreps[(size_t)gi * KTOP * LD + (size_t)(rb * 16 + r0 + rr) * LD + col] = acc[rr];
}

// ---------------- kernel 8: ops -> conv -> relu -> maxpool -> alpha mix ----
__global__ void __launch_bounds__(256) k_mix(const float* __restrict__ convk,
                                             const float* __restrict__ convb,
                                             const float* __restrict__ logalpha) {
    int gi = blockIdx.x, tid = threadIdx.x;
    int tx = tid & 15, ty = tid >> 4;
    __shared__ float S[64][66];
    __shared__ float Bt[16][128];
    __shared__ float Pb[16][64];
    __shared__ float Red[16][64];
    __shared__ float gm[64], cb[64], alpha[3], feats[3][64];

    for (int i = tid; i < 4096; i += 256)
        S[i >> 6][i & 63] = d_subreps[(size_t)gi * 4096 + i];
    if (tid < 64) { gm[tid] = d_gmean[gi * LD + tid]; cb[tid] = convb[tid]; }
    if (tid == 0) {
        float a0 = logalpha[0], a1 = logalpha[1], a2 = logalpha[2];
        float m = fmaxf(a0, fmaxf(a1, a2));
        float e0 = expf(a0 - m), e1 = expf(a1 - m), e2 = expf(a2 - m);
        float inv = 1.0f / (e0 + e1 + e2);
        alpha[0] = e0 * inv; alpha[1] = e1 * inv; alpha[2] = e2 * inv;
    }
    __syncthreads();

    const int oorder[3] = {0, 2, 1};
    for (int oo = 0; oo < 3; oo++) {
        int o = oorder[oo];
        if (o == 1) {
            __syncthreads();
            for (int i = tid; i < 4096; i += 256) {
                float v = S[i >> 6][i & 63];
                S[i >> 6][i & 63] = (v > 0.f) ? v : expm1f(v);
            }
        }
        float aq[4][4], ap[4][4];
        #pragma unroll
        for (int r = 0; r < 4; r++)
            #pragma unroll
            for (int c = 0; c < 4; c++) { aq[r][c] = 0.f; ap[r][c] = 0.f; }

        for (int l0 = 0; l0 < 64; l0 += 16) {
            __syncthreads();
            #pragma unroll
            for (int t = 0; t < 2; t++) {
                int s = tid + t * 256;
                int lr = s >> 5, cq = s & 31;
                int dd = cq * 4;
                const float* src = (dd < 64)
                    ? (convk + (size_t)(l0 + lr) * 64 + dd)
                    : (convk + 4096 + (size_t)(l0 + lr) * 64 + (dd - 64));
                *(float4*)&Bt[lr][dd] = *(const float4*)src;
            }
            __syncthreads();
            #pragma unroll
            for (int l = 0; l < 16; l++) {
                float a[4];
                #pragma unroll
                for (int r = 0; r < 4; r++) {
                    float v = S[ty * 4 + r][l0 + l];
                    a[r] = (o == 2) ? v + gm[l0 + l] : v;
                }
                float4 bq = *(const float4*)&Bt[l][tx * 4];
                float4 bp = *(const float4*)&Bt[l][64 + tx * 4];
                #pragma unroll
                for (int r = 0; r < 4; r++) {
                    aq[r][0] = fmaf(a[r], bq.x, aq[r][0]);
                    aq[r][1] = fmaf(a[r], bq.y, aq[r][1]);
                    aq[r][2] = fmaf(a[r], bq.z, aq[r][2]);
                    aq[r][3] = fmaf(a[r], bq.w, aq[r][3]);
                    ap[r][0] = fmaf(a[r], bp.x, ap[r][0]);
                    ap[r][1] = fmaf(a[r], bp.y, ap[r][1]);
                    ap[r][2] = fmaf(a[r], bp.z, ap[r][2]);
                    ap[r][3] = fmaf(a[r], bp.w, ap[r][3]);
                }
            }
        }
        __syncthreads();
        #pragma unroll
        for (int c = 0; c < 4; c++) Pb[ty][tx * 4 + c] = ap[0][c];
        __syncthreads();
        float vm[4] = {0.f, 0.f, 0.f, 0.f};
        #pragma unroll
        for (int r = 0; r < 4; r++) {
            int k = ty * 4 + r;
            if (k <= 62) {
                float pn[4];
                if (r < 3) {
                    #pragma unroll
                    for (int c = 0; c < 4; c++) pn[c] = ap[r + 1][c];
                } else {
                    #pragma unroll
                    for (int c = 0; c < 4; c++) pn[c] = Pb[ty + 1][tx * 4 + c];
                }
                #pragma unroll
                for (int c = 0; c < 4; c++) {
                    float v = aq[r][c] + pn[c] + cb[tx * 4 + c];
                    v = fmaxf(v, 0.f);
                    vm[c] = fmaxf(vm[c], v);
                }
            }
        }
        #pragma unroll
        for (int c = 0; c < 4; c++) Red[ty][tx * 4 + c] = vm[c];
        __syncthreads();
        if (ty == 0) {
            #pragma unroll
            for (int c = 0; c < 4; c++) {
                float m = 0.f;
                #pragma unroll
                for (int yy = 0; yy < 16; yy++) m = fmaxf(m, Red[yy][tx * 4 + c]);
                feats[o][tx * 4 + c] = m;
            }
        }
        __syncthreads();
    }
    if (tid < 64)
        d_Bout[gi * LD + tid] = alpha[0] * feats[0][tid]
                              + alpha[1] * feats[1][tid]
                              + alpha[2] * feats[2][tid];
}

// ---------------- kernel 9: discriminator epilogue --------------------------
__global__ void k_final(const float* __restrict__ original,
                        const float* __restrict__ Wd,
                        float* __restrict__ out) {
    int tid = threadIdx.x;
    __shared__ float sO[32][64];
    __shared__ float sW[64][64];
    __shared__ float sWc[32][64];
    __shared__ float sB[32][64];
    for (int i = tid; i < 2048; i += 256) {
        sO[i >> 6][i & 63] = original[i];
        sB[i >> 6][i & 63] = d_Bout[i];
    }
    for (int i = tid; i < 4096; i += 256) sW[i >> 6][i & 63] = Wd[i];
    __syncthreads();
    for (int i = tid; i < 2048; i += 256) {
        int gi = i >> 6, d = i & 63;
        float s = 0.f;
        #pragma unroll
        for (int l = 0; l < 64; l++) s = fmaf(sO[gi][l], sW[l][d], s);
        sWc[gi][d] = s;
    }
    __syncthreads();
    if (tid < 32) {
        int i = tid, j = (tid + 31) & 31;
        float s1 = 0.f, s2 = 0.f;
        #pragma unroll
        for (int d = 0; d < 64; d++) {
            s1 = fmaf(sB[i][d], sWc[i][d], s1);
            s2 = fmaf(sB[j][d], sWc[i][d], s2);
        }
        out[i] = s1;
        out[32 + i] = s2;
    }
}

// ---------------- launch ----------------------------------------------------
extern "C" void kernel_launch(void* const* d_in, const int* in_sizes, int n_in,
                              void* d_out, int out_size) {
    const float* original  = (const float*)d_in[0];
    const float* x         = (const float*)d_in[1];
    const float* g         = (const float*)d_in[2];
    const float* W_gcn     = (const float*)d_in[3];
    const float* b_gcn     = (const float*)d_in[4];
    const float* p_select  = (const float*)d_in[5];
    const float* conv_k    = (const float*)d_in[6];
    const float* conv_b    = (const float*)d_in[7];
    const float* W_disc    = (const float*)d_in[8];
    const float* log_alpha = (const float*)d_in[9];
    float* out = (float*)d_out;

    const int hn_smem = 2 * 2 * 64 * BP * 2;   // 69632 bytes
    cudaFuncSetAttribute(k_hn_mma, cudaFuncAttributeMaxDynamicSharedMemorySize, hn_smem);

    k_deg<<<(G * NN) / 8, 256>>>(g);
    k_xw<<<G * (NN / 128), 128>>>(x, W_gcn);
    k_prepB<<<G * 32, 256>>>();
    k_hn_mma<<<G * 16, 256, hn_smem>>>(g, b_gcn, p_select);
    k_topk<<<G, 1024>>>();
    k_sub<<<G * 4, 256>>>(g);
    k_mix<<<G, 256>>>(conv_k, conv_b, log_alpha);
    k_final<<<1, 256>>>(original, W_disc, out);
}